// round 11
// baseline (speedup 1.0000x reference)
#include <cuda_runtime.h>
#include <cuda_fp16.h>
#include <math.h>
#include <stdint.h>

// ---------------------------------------------------------------------------
// Problem dimensions (fixed by the dataset)
// ---------------------------------------------------------------------------
#define BB   16
#define TT   1500
#define DD   1024
#define DH   1023
#define DTXT 4096
#define NTOK 375
#define MM   (BB*NTOK)     // 6000
#define MAXP 12288
#define LDH  1024

// ---------------------------------------------------------------------------
// Device scratch
// ---------------------------------------------------------------------------
__device__ float g_numpred[BB];
__device__ int   g_nf[BB];
__device__ int   g_nt[BB];
__device__ int2  g_pairs[BB*MAXP];              // {t, w_bits}; n implied by rowptr
__device__ int   g_rowptr[BB*(NTOK+1)];
__device__ float g_h2 [(size_t)MM*DD];          // cif_proj out
__device__ __half g_ahi[(size_t)MM*LDH];        // A hi
__device__ __half g_alo[(size_t)MM*LDH];        // A lo (cif_proj only)
__device__ __half g_bhi[(size_t)DTXT*DD];       // B hi

// ---------------------------------------------------------------------------
__device__ __forceinline__ void split_h(float x, __half& h, __half& l) {
    h = __float2half(x);
    l = __float2half(x - __half2float(h));
}

// ---------------------------------------------------------------------------
// Kernel 0: int64/int32 detection
// ---------------------------------------------------------------------------
__global__ void k_detect(const void* nf_raw, const void* nt_raw) {
    const int* a = (const int*)nf_raw;
    const int* b = (const int*)nt_raw;
    bool is64 = (a[1] == 0) && (a[3] == 0) && (a[5] == 0);
    for (int i = 0; i < BB; i++) {
        if (is64) {
            g_nf[i] = (int)((const long long*)nf_raw)[i];
            g_nt[i] = (int)((const long long*)nt_raw)[i];
        } else {
            g_nf[i] = a[i];
            g_nt[i] = b[i];
        }
    }
}

// ---------------------------------------------------------------------------
// Kernel CIF v4: fused alphas + vote-free exact scan with fallback.
// ---------------------------------------------------------------------------
#define CIF_SMEM (BB*TT*4 + BB*(NTOK+1)*4)   // 120064 B

__global__ void __launch_bounds__(512) k_cif4(const float* __restrict__ af) {
    extern __shared__ char cs[];
    float* sal   = (float*)cs;                  // [BB*TT]
    int*   slast = (int*)(cs + BB*TT*4);        // [BB*(NTOK+1)]
    int tid = threadIdx.x;
    int w = tid >> 5, lane = tid & 31;

    // ---- phase A: warp w handles batch w ----
    {
        int b = w;
        int nf = g_nf[b];
        float s = 0.f;
        for (int t = lane; t < TT; t += 32) {
            float x  = af[((size_t)b*TT + t)*DD + (DD-1)];
            float sg = 1.0f / (1.0f + expf(-x));
            if (t >= nf) sg = 0.f;
            sal[b*TT + t] = sg;
            s += sg;
        }
        #pragma unroll
        for (int o = 16; o > 0; o >>= 1)
            s += __shfl_xor_sync(0xFFFFFFFFu, s, o);
        if (lane == 0) g_numpred[b] = s;
        float scale = (float)g_nt[b] / s;
        for (int t = lane; t < TT; t += 32)
            sal[b*TT + t] *= scale;
    }
    __syncthreads();
    for (int i = tid; i < BB*(NTOK+1); i += 512) slast[i] = 0;
    __syncthreads();

    // ---- phase B: exact scan (warp 0, lanes 0..15) ----
    if (tid < BB) {
        const unsigned FULL = 0xFFFFu;
        int b = tid;
        const float* al = sal + b*TT;
        int* lrow = slast + b*(NTOK+1);
        int base = b * MAXP;
        int nt1 = g_nt[b] - 1;

        float integrate = 0.f;
        int idx = 0, pcnt = 0;
        float p_w0 = 0.f, p_w1 = 0.f;
        int   p_n0 = 0,   p_n1 = 0;
        bool  efire = false;

        float a = al[0];
        #pragma unroll 4
        for (int t = 0; t < TT; t++) {
            float a_next = al[(t + 1 < TT) ? t + 1 : t];   // prefetch off the chain
            if (t > 0) {
                if (p_w0 != 0.f) {
                    g_pairs[base+pcnt] = make_int2(t-1, __float_as_int(p_w0));
                    lrow[p_n0] = ++pcnt;
                }
                if (p_w1 != 0.f) {
                    g_pairs[base+pcnt] = make_int2(t-1, __float_as_int(p_w1));
                    lrow[p_n1] = ++pcnt;
                }
            }
            float an = 1.f - integrate;
            integrate += a;
            bool ready = (integrate >= 1.f);
            float aint = ready ? an : a;
            if (ready) integrate -= 1.f;
            p_n0 = idx; p_w0 = aint;
            p_w1 = a - aint;
            if (ready) idx = min(idx + 1, nt1);
            p_n1 = idx;
            efire |= (integrate >= 1.f);
            a = a_next;
        }
        if (p_w0 != 0.f) {
            g_pairs[base+pcnt] = make_int2(TT-1, __float_as_int(p_w0));
            lrow[p_n0] = ++pcnt;
        }

        // ---- slow-path fallback (bit-exact reference semantics w/ votes) ----
        bool slow = __any_sync(FULL, efire);
        if (slow) {
            for (int n = 0; n <= NTOK; n++) lrow[n] = 0;
            integrate = 0.f; idx = 0; pcnt = 0;
            float prem = 0.f;
            int pn[6]; float pw[6]; int pc = 0;
            for (int t = 0; t < TT; t++) {
                if (t > 0) {
                    if (prem != 0.f) {
                        #pragma unroll
                        for (int j = 0; j < 6; j++)
                            if (j == pc) { pn[j] = idx; pw[j] = prem; }
                        if (pc < 6) pc++;
                    }
                    #pragma unroll
                    for (int i = 0; i < 6; i++) {
                        if (i < pc && pw[i] != 0.f && pcnt < MAXP) {
                            g_pairs[base+pcnt] = make_int2(t-1, __float_as_int(pw[i]));
                            lrow[pn[i]] = pcnt + 1; pcnt++;
                        }
                    }
                    pc = 0;
                }
                float av = al[t];
                float an = 1.f - integrate;
                integrate += av;
                bool ready = (integrate >= 1.f);
                if (ready) integrate -= 1.f;
                float aint = ready ? an : av;
                pn[0] = idx; pw[0] = aint; pc = 1;
                prem = av - aint;
                if (ready) idx = min(idx + 1, nt1);
                #pragma unroll
                for (int e = 0; e < 3; e++) {
                    bool any = __any_sync(FULL, integrate >= 1.f);
                    if (any) {
                        bool r2 = (integrate >= 1.f);
                        if (r2) integrate -= 1.f;
                        float ai2 = r2 ? 1.f : prem;
                        bool found = false;
                        #pragma unroll
                        for (int j = 0; j < 6; j++)
                            if (j < pc && pn[j] == idx && !found) { pw[j] = ai2; found = true; }
                        if (!found) {
                            #pragma unroll
                            for (int j = 0; j < 6; j++)
                                if (j == pc) { pn[j] = idx; pw[j] = ai2; }
                            if (pc < 6) pc++;
                        }
                        prem = prem - ai2;
                        if (r2) idx = min(idx + 1, nt1);
                    }
                }
            }
            #pragma unroll
            for (int i = 0; i < 6; i++) {
                if (i < pc && pw[i] != 0.f && pcnt < MAXP) {
                    g_pairs[base+pcnt] = make_int2(TT-1, __float_as_int(pw[i]));
                    lrow[pn[i]] = pcnt + 1; pcnt++;
                }
            }
        } else {
            __any_sync(FULL, false);
        }

        int* rp = &g_rowptr[b*(NTOK+1)];
        rp[0] = 0;
        int p = 0;
        for (int n = 0; n < NTOK; n++) {
            int v = lrow[n];
            if (v > 0) p = v;
            rp[n+1] = p;
        }
    }
}

// ---------------------------------------------------------------------------
// Kernel 3: h1 = CIF sparse sum, written as fp16 hi/lo splits
// ---------------------------------------------------------------------------
__global__ void k_h1(const float* __restrict__ af) {
    int r = blockIdx.x;
    int b = r / NTOK, n = r % NTOK;
    int s = g_rowptr[b*(NTOK+1) + n];
    int e = g_rowptr[b*(NTOK+1) + n + 1];
    int d = threadIdx.x;
    float a0 = 0.f, a1 = 0.f, a2 = 0.f, a3 = 0.f;
    for (int p = s; p < e; p++) {
        int2 pr = g_pairs[b*MAXP + p];
        int   t = pr.x;
        float w = __int_as_float(pr.y);
        const float* row = af + ((size_t)b*TT + t)*DD;
        a0 += w * row[d];
        a1 += w * row[d + 256];
        a2 += w * row[d + 512];
        if (d + 768 < DH) a3 += w * row[d + 768];
    }
    size_t o = (size_t)r*LDH;
    __half h, l;
    split_h(a0, h, l); g_ahi[o+d]     = h; g_alo[o+d]     = l;
    split_h(a1, h, l); g_ahi[o+d+256] = h; g_alo[o+d+256] = l;
    split_h(a2, h, l); g_ahi[o+d+512] = h; g_alo[o+d+512] = l;
    if (d + 768 < DH) { split_h(a3, h, l); g_ahi[o+d+768] = h; g_alo[o+d+768] = l; }
    else { g_ahi[o+1023] = __float2half(0.f); g_alo[o+1023] = __float2half(0.f); }
}

// ---------------------------------------------------------------------------
__global__ void k_padw_hi(const float* __restrict__ w) {
    int i = blockIdx.x * 256 + threadIdx.x;
    int n = i >> 10, k = i & 1023;
    float v = (k < DH) ? w[(size_t)n*DH + k] : 0.f;
    g_bhi[i] = __float2half(v);
}
__global__ void k_w_hi(const float* __restrict__ w) {
    int i = blockIdx.x * 256 + threadIdx.x;
    g_bhi[i] = __float2half(w[i]);
}

// ---------------------------------------------------------------------------
// Kernel 5: RMSNorm on g_h2, write normalized rows as fp16 hi only
// ---------------------------------------------------------------------------
__global__ void k_rms(const float* __restrict__ lnw) {
    int r = blockIdx.x;
    const float* hp = g_h2 + (size_t)r*DD;
    int tid = threadIdx.x;
    float v0 = hp[tid], v1 = hp[tid+256], v2 = hp[tid+512], v3 = hp[tid+768];
    __shared__ float red[256];
    red[tid] = v0*v0 + v1*v1 + v2*v2 + v3*v3;
    __syncthreads();
    for (int o = 128; o > 0; o >>= 1) {
        if (tid < o) red[tid] += red[tid + o];
        __syncthreads();
    }
    float inv = rsqrtf(red[0] * (1.0f/DD) + 1e-6f);
    size_t o = (size_t)r*DD;
    g_ahi[o+tid]     = __float2half(v0*inv*lnw[tid]);
    g_ahi[o+tid+256] = __float2half(v1*inv*lnw[tid+256]);
    g_ahi[o+tid+512] = __float2half(v2*inv*lnw[tid+512]);
    g_ahi[o+tid+768] = __float2half(v3*inv*lnw[tid+768]);
}

// ---------------------------------------------------------------------------
// fp16 tensor-core GEMM (mma.sync.m16n8k16, pre-split operands).
// Template over NPASS (A plain / A hi+lo) and BN (128 or 256).
// CTA tile 128 x BN, BK=32, 256 threads; warp tile 64 x (BN/4).
// ---------------------------------------------------------------------------
#define ASTRIDE   40                       // smem row stride in halves (80 B)
#define AROWB     80
#define ATILEB    (128*AROWB)              // 10240 B (A part tile)

__device__ __forceinline__ void cp16(uint32_t dst, const void* src) {
    asm volatile("cp.async.cg.shared.global [%0], [%1], 16;"
                 :: "r"(dst), "l"(src) : "memory");
}
__device__ __forceinline__ void ldsm4(uint32_t r[4], uint32_t addr) {
    asm volatile("ldmatrix.sync.aligned.m8n8.x4.shared.b16 {%0,%1,%2,%3}, [%4];"
                 : "=r"(r[0]), "=r"(r[1]), "=r"(r[2]), "=r"(r[3]) : "r"(addr));
}
__device__ __forceinline__ void mma_h(float d[4], const uint32_t a[4],
                                      uint32_t b0, uint32_t b1) {
    asm volatile(
        "mma.sync.aligned.m16n8k16.row.col.f32.f16.f16.f32 "
        "{%0,%1,%2,%3}, {%4,%5,%6,%7}, {%8,%9}, {%0,%1,%2,%3};"
        : "+f"(d[0]), "+f"(d[1]), "+f"(d[2]), "+f"(d[3])
        : "r"(a[0]), "r"(a[1]), "r"(a[2]), "r"(a[3]), "r"(b0), "r"(b1));
}

template<int NPASS, int BN>
__global__ void __launch_bounds__(256)
gemm_h(int M, int K,
       const __half* __restrict__ Ah, const __half* __restrict__ Al, int lda,
       const __half* __restrict__ Bh, int ldb,
       const float* __restrict__ bias,
       float* __restrict__ C, int ldc)
{
    constexpr int NA = (NPASS == 2) ? 2 : 1;
    constexpr int BTILEB = BN * AROWB;
    constexpr uint32_t STAGEB = NA*ATILEB + BTILEB;
    constexpr int NI = BN / 32;            // n-subtiles per warp (8-wide each)
    constexpr int NB = NI / 2;             // 16-wide ldsm groups
    extern __shared__ __align__(128) char smem[];
    uint32_t sbase = (uint32_t)__cvta_generic_to_shared(smem);

    int tid  = threadIdx.x;
    int wid  = tid >> 5, lane = tid & 31;
    int g    = lane >> 2, tig = lane & 3;
    int m0   = blockIdx.y * 128;
    int n0   = blockIdx.x * BN;
    int wm   = (wid & 1) * 64;
    int wn   = (wid >> 1) * (BN/4);

    float acc[4][NI][4];
    #pragma unroll
    for (int i = 0; i < 4; i++)
        #pragma unroll
        for (int j = 0; j < NI; j++)
            #pragma unroll
            for (int q = 0; q < 4; q++) acc[i][j][q] = 0.f;

    const int nt = K >> 5;

    auto load_stage = [&](int s, int kt) {
        uint32_t st = sbase + (uint32_t)s * STAGEB;
        int k0 = kt << 5;
        #pragma unroll
        for (int c = tid; c < 512; c += 256) {       // A: 128 rows x 4 chunks
            int row = c >> 2, ch = (c & 3) << 4;
            int ke = k0 + (ch >> 1);
            int gm = m0 + row; if (gm >= M) gm = M - 1;
            uint32_t d = st + row*AROWB + ch;
            cp16(d, Ah + (size_t)gm*lda + ke);
            if (NPASS == 2) cp16(d + ATILEB, Al + (size_t)gm*lda + ke);
        }
        #pragma unroll
        for (int c = tid; c < BN*4; c += 256) {      // B: BN rows x 4 chunks
            int row = c >> 2, ch = (c & 3) << 4;
            int ke = k0 + (ch >> 1);
            cp16(st + NA*ATILEB + row*AROWB + ch, Bh + (size_t)(n0 + row)*ldb + ke);
        }
        asm volatile("cp.async.commit_group;" ::: "memory");
    };

    load_stage(0, 0);

    int quad = lane >> 3, qr = lane & 7;
    for (int kt = 0; kt < nt; kt++) {
        int buf = kt & 1;
        if (kt + 1 < nt) {
            load_stage(buf ^ 1, kt + 1);
            asm volatile("cp.async.wait_group 1;" ::: "memory");
        } else {
            asm volatile("cp.async.wait_group 0;" ::: "memory");
        }
        __syncthreads();

        uint32_t st = sbase + (uint32_t)buf * STAGEB;
        #pragma unroll
        for (int ks = 0; ks < 2; ks++) {
            int kc = ks * 16;
            uint32_t ka = (uint32_t)((kc + ((quad >> 1) << 3)) << 1);
            uint32_t arow = st + (uint32_t)(wm + ((quad & 1) << 3) + qr) * AROWB + ka;
            uint32_t brow = st + NA*ATILEB
                          + (uint32_t)(wn + ((quad & 1) << 3) + qr) * AROWB + ka;

            uint32_t ah[4][4], al[4][4], bh[NB][4];
            #pragma unroll
            for (int mi = 0; mi < 4; mi++) {
                ldsm4(ah[mi], arow + mi*16*AROWB);
                if (NPASS == 2) ldsm4(al[mi], arow + ATILEB + mi*16*AROWB);
            }
            #pragma unroll
            for (int nb = 0; nb < NB; nb++)
                ldsm4(bh[nb], brow + nb*16*AROWB);

            #pragma unroll
            for (int mi = 0; mi < 4; mi++)
                #pragma unroll
                for (int ni = 0; ni < NI; ni++) {
                    int nb = ni >> 1, sel = ni & 1;
                    mma_h(acc[mi][ni], ah[mi], bh[nb][sel], bh[nb][sel+2]);
                    if (NPASS == 2)
                        mma_h(acc[mi][ni], al[mi], bh[nb][sel], bh[nb][sel+2]);
                }
        }
        __syncthreads();
    }

    #pragma unroll
    for (int mi = 0; mi < 4; mi++) {
        int row0 = m0 + wm + mi*16 + g;
        int row1 = row0 + 8;
        #pragma unroll
        for (int ni = 0; ni < NI; ni++) {
            int col = n0 + wn + ni*8 + 2*tig;
            float b0 = bias[col], b1 = bias[col+1];
            if (row0 < M) {
                float2 v = { acc[mi][ni][0] + b0, acc[mi][ni][1] + b1 };
                *reinterpret_cast<float2*>(C + (size_t)row0*ldc + col) = v;
            }
            if (row1 < M) {
                float2 v = { acc[mi][ni][2] + b0, acc[mi][ni][3] + b1 };
                *reinterpret_cast<float2*>(C + (size_t)row1*ldc + col) = v;
            }
        }
    }
}

// ---------------------------------------------------------------------------
__global__ void k_tail(float* __restrict__ out, int out_size) {
    int i = threadIdx.x;
    if (i < BB && out_size >= MM*DTXT + 2*BB) {
        out[MM*DTXT + i]      = (float)g_nt[i];
        out[MM*DTXT + BB + i] = g_numpred[i];
    }
}

// ---------------------------------------------------------------------------
extern "C" void kernel_launch(void* const* d_in, const int* in_sizes, int n_in,
                              void* d_out, int out_size) {
    const float* af     = (const float*)d_in[0];
    const float* cif_w  = (const float*)d_in[1];
    const float* cif_b  = (const float*)d_in[2];
    const float* ln_w   = (const float*)d_in[3];
    const float* text_w = (const float*)d_in[4];
    const float* text_b = (const float*)d_in[5];
    const void*  nf     = d_in[6];
    const void*  nt     = d_in[7];
    float* out = (float*)d_out;

    void *p_h2=0, *p_ahi=0, *p_alo=0, *p_bhi=0;
    cudaGetSymbolAddress(&p_h2,  g_h2);
    cudaGetSymbolAddress(&p_ahi, g_ahi);
    cudaGetSymbolAddress(&p_alo, g_alo);
    cudaGetSymbolAddress(&p_bhi, g_bhi);

    const int SMEM2 = 2 * (2*ATILEB + 128*AROWB);   // NPASS2/BN128: 61440
    const int SMEM1 = 2 * (ATILEB + 256*AROWB);     // NPASS1/BN256: 61440
    cudaFuncSetAttribute((const void*)gemm_h<2,128>, cudaFuncAttributeMaxDynamicSharedMemorySize, SMEM2);
    cudaFuncSetAttribute((const void*)gemm_h<1,256>, cudaFuncAttributeMaxDynamicSharedMemorySize, SMEM1);
    cudaFuncSetAttribute((const void*)k_cif4,        cudaFuncAttributeMaxDynamicSharedMemorySize, CIF_SMEM);

    k_detect<<<1, 1>>>(nf, nt);
    k_cif4<<<1, 512, CIF_SMEM>>>(af);
    k_h1<<<MM, 256>>>(af);                          // -> g_ahi/g_alo (fp16)
    k_padw_hi<<<(DD*DD)/256, 256>>>(cif_w);         // -> g_bhi (fp16)

    // cif_proj: 2-pass (A split, B fp16), BN=128
    {
        dim3 grid(DD/128, (MM + 127)/128);
        gemm_h<2,128><<<grid, 256, SMEM2>>>(MM, 1024,
            (const __half*)p_ahi, (const __half*)p_alo, LDH,
            (const __half*)p_bhi, 1024,
            cif_b, (float*)p_h2, DD);
    }
    k_rms<<<MM, 256>>>(ln_w);                       // g_h2 -> g_ahi (hi only)
    k_w_hi<<<(DTXT*DD)/256, 256>>>(text_w);         // -> g_bhi

    // text_proj: 1-pass fp16, BN=256 (wide warp tile)
    {
        dim3 grid(DTXT/256, (MM + 127)/128);
        gemm_h<1,256><<<grid, 256, SMEM1>>>(MM, 1024,
            (const __half*)p_ahi, (const __half*)p_alo, DD,
            (const __half*)p_bhi, DD,
            text_b, out, DTXT);
    }
    k_tail<<<1, 32>>>(out, out_size);
}

// round 12
// speedup vs baseline: 1.3109x; 1.3109x over previous
#include <cuda_runtime.h>
#include <cuda_fp16.h>
#include <math.h>
#include <stdint.h>

#define BB   16
#define TT   1500
#define DD   1024
#define DH   1023
#define DTXT 4096
#define NTOK 375
#define MM   (BB*NTOK)     // 6000
#define MAXP 12288
#define LDH  1024

// ---------------------------------------------------------------------------
// Device scratch
// ---------------------------------------------------------------------------
__device__ float g_numpred[BB];
__device__ int   g_nf[BB];
__device__ int   g_nt[BB];
__device__ int2  g_pairs[BB*MAXP];
__device__ int   g_rowptr[BB*(NTOK+1)];
__device__ int   g_rowmap[MM];                  // compact -> b*NTOK+n
__device__ int   g_Mp[1];                       // M' = sum(nt)
__device__ float g_h2 [(size_t)MM*DD];
__device__ __half g_ahi[(size_t)MM*LDH];
__device__ __half g_alo[(size_t)MM*LDH];
__device__ __half g_bhi[(size_t)DTXT*DD];
__device__ float g_embed[DD];                   // rmsnorm(cif_b)*ln_w
__device__ float g_outempty[DTXT];              // shared empty-row output

__device__ __forceinline__ void split_h(float x, __half& h, __half& l) {
    h = __float2half(x);
    l = __float2half(x - __half2float(h));
}

// ---------------------------------------------------------------------------
__global__ void k_detect(const void* nf_raw, const void* nt_raw) {
    const int* a = (const int*)nf_raw;
    const int* b = (const int*)nt_raw;
    bool is64 = (a[1] == 0) && (a[3] == 0) && (a[5] == 0);
    for (int i = 0; i < BB; i++) {
        if (is64) {
            g_nf[i] = (int)((const long long*)nf_raw)[i];
            g_nt[i] = (int)((const long long*)nt_raw)[i];
        } else {
            g_nf[i] = a[i];
            g_nt[i] = b[i];
        }
    }
}

// ---------------------------------------------------------------------------
// CIF v5: fused alphas + vote-free exact scan + compact row map build.
// ---------------------------------------------------------------------------
#define CIF_SMEM (BB*TT*4 + BB*(NTOK+1)*4)

__global__ void __launch_bounds__(512) k_cif5(const float* __restrict__ af) {
    extern __shared__ char cs[];
    float* sal   = (float*)cs;
    int*   slast = (int*)(cs + BB*TT*4);
    __shared__ int s_off[BB+1];
    int tid = threadIdx.x;
    int w = tid >> 5, lane = tid & 31;

    // phase A: warp w = batch w
    {
        int b = w;
        int nf = g_nf[b];
        float s = 0.f;
        for (int t = lane; t < TT; t += 32) {
            float x  = af[((size_t)b*TT + t)*DD + (DD-1)];
            float sg = 1.0f / (1.0f + expf(-x));
            if (t >= nf) sg = 0.f;
            sal[b*TT + t] = sg;
            s += sg;
        }
        #pragma unroll
        for (int o = 16; o > 0; o >>= 1)
            s += __shfl_xor_sync(0xFFFFFFFFu, s, o);
        if (lane == 0) g_numpred[b] = s;
        float scale = (float)g_nt[b] / s;
        for (int t = lane; t < TT; t += 32)
            sal[b*TT + t] *= scale;
    }
    if (tid == 0) {
        s_off[0] = 0;
        for (int b = 0; b < BB; b++) s_off[b+1] = s_off[b] + g_nt[b];
        g_Mp[0] = s_off[BB];
    }
    __syncthreads();
    // rowmap: warp w fills its batch
    {
        int b = w, o = s_off[b], n_t = g_nt[b];
        for (int n = lane; n < n_t; n += 32)
            g_rowmap[o + n] = b*NTOK + n;
    }
    for (int i = tid; i < BB*(NTOK+1); i += 512) slast[i] = 0;
    __syncthreads();

    // phase B: exact scan (warp 0, lanes 0..15)
    if (tid < BB) {
        const unsigned FULL = 0xFFFFu;
        int b = tid;
        const float* al = sal + b*TT;
        int* lrow = slast + b*(NTOK+1);
        int base = b * MAXP;
        int nt1 = g_nt[b] - 1;

        float integrate = 0.f;
        int idx = 0, pcnt = 0;
        float p_w0 = 0.f, p_w1 = 0.f;
        int   p_n0 = 0,   p_n1 = 0;
        bool  efire = false;

        float a = al[0];
        #pragma unroll 4
        for (int t = 0; t < TT; t++) {
            float a_next = al[(t + 1 < TT) ? t + 1 : t];
            if (t > 0) {
                if (p_w0 != 0.f) {
                    g_pairs[base+pcnt] = make_int2(t-1, __float_as_int(p_w0));
                    lrow[p_n0] = ++pcnt;
                }
                if (p_w1 != 0.f) {
                    g_pairs[base+pcnt] = make_int2(t-1, __float_as_int(p_w1));
                    lrow[p_n1] = ++pcnt;
                }
            }
            float an = 1.f - integrate;
            integrate += a;
            bool ready = (integrate >= 1.f);
            float aint = ready ? an : a;
            if (ready) integrate -= 1.f;
            p_n0 = idx; p_w0 = aint;
            p_w1 = a - aint;
            if (ready) idx = min(idx + 1, nt1);
            p_n1 = idx;
            efire |= (integrate >= 1.f);
            a = a_next;
        }
        if (p_w0 != 0.f) {
            g_pairs[base+pcnt] = make_int2(TT-1, __float_as_int(p_w0));
            lrow[p_n0] = ++pcnt;
        }

        // slow-path fallback (bit-exact reference semantics; never taken)
        bool slow = __any_sync(FULL, efire);
        if (slow) {
            for (int n = 0; n <= NTOK; n++) lrow[n] = 0;
            integrate = 0.f; idx = 0; pcnt = 0;
            float prem = 0.f;
            int pn[6]; float pw[6]; int pc = 0;
            for (int t = 0; t < TT; t++) {
                if (t > 0) {
                    if (prem != 0.f) {
                        #pragma unroll
                        for (int j = 0; j < 6; j++)
                            if (j == pc) { pn[j] = idx; pw[j] = prem; }
                        if (pc < 6) pc++;
                    }
                    #pragma unroll
                    for (int i = 0; i < 6; i++) {
                        if (i < pc && pw[i] != 0.f && pcnt < MAXP) {
                            g_pairs[base+pcnt] = make_int2(t-1, __float_as_int(pw[i]));
                            lrow[pn[i]] = pcnt + 1; pcnt++;
                        }
                    }
                    pc = 0;
                }
                float av = al[t];
                float an = 1.f - integrate;
                integrate += av;
                bool ready = (integrate >= 1.f);
                if (ready) integrate -= 1.f;
                float aint = ready ? an : av;
                pn[0] = idx; pw[0] = aint; pc = 1;
                prem = av - aint;
                if (ready) idx = min(idx + 1, nt1);
                #pragma unroll
                for (int e = 0; e < 3; e++) {
                    bool any = __any_sync(FULL, integrate >= 1.f);
                    if (any) {
                        bool r2 = (integrate >= 1.f);
                        if (r2) integrate -= 1.f;
                        float ai2 = r2 ? 1.f : prem;
                        bool found = false;
                        #pragma unroll
                        for (int j = 0; j < 6; j++)
                            if (j < pc && pn[j] == idx && !found) { pw[j] = ai2; found = true; }
                        if (!found) {
                            #pragma unroll
                            for (int j = 0; j < 6; j++)
                                if (j == pc) { pn[j] = idx; pw[j] = ai2; }
                            if (pc < 6) pc++;
                        }
                        prem = prem - ai2;
                        if (r2) idx = min(idx + 1, nt1);
                    }
                }
            }
            #pragma unroll
            for (int i = 0; i < 6; i++) {
                if (i < pc && pw[i] != 0.f && pcnt < MAXP) {
                    g_pairs[base+pcnt] = make_int2(TT-1, __float_as_int(pw[i]));
                    lrow[pn[i]] = pcnt + 1; pcnt++;
                }
            }
        } else {
            __any_sync(FULL, false);
        }

        int* rp = &g_rowptr[b*(NTOK+1)];
        rp[0] = 0;
        int p = 0;
        for (int n = 0; n < NTOK; n++) {
            int v = lrow[n];
            if (v > 0) p = v;
            rp[n+1] = p;
        }
    }
}

// ---------------------------------------------------------------------------
// k_h1 (compact): block r < M' handles compact row r = (b,n) via rowmap
// ---------------------------------------------------------------------------
__global__ void k_h1(const float* __restrict__ af) {
    int r = blockIdx.x;
    if (r >= g_Mp[0]) return;
    int bn = g_rowmap[r];
    int b = bn / NTOK, n = bn % NTOK;
    int s = g_rowptr[b*(NTOK+1) + n];
    int e = g_rowptr[b*(NTOK+1) + n + 1];
    int d = threadIdx.x;
    float a0 = 0.f, a1 = 0.f, a2 = 0.f, a3 = 0.f;
    for (int p = s; p < e; p++) {
        int2 pr = g_pairs[b*MAXP + p];
        float w = __int_as_float(pr.y);
        const float* row = af + ((size_t)b*TT + pr.x)*DD;
        a0 += w * row[d];
        a1 += w * row[d + 256];
        a2 += w * row[d + 512];
        if (d + 768 < DH) a3 += w * row[d + 768];
    }
    size_t o = (size_t)r*LDH;
    __half h, l;
    split_h(a0, h, l); g_ahi[o+d]     = h; g_alo[o+d]     = l;
    split_h(a1, h, l); g_ahi[o+d+256] = h; g_alo[o+d+256] = l;
    split_h(a2, h, l); g_ahi[o+d+512] = h; g_alo[o+d+512] = l;
    if (d + 768 < DH) { split_h(a3, h, l); g_ahi[o+d+768] = h; g_alo[o+d+768] = l; }
    else { g_ahi[o+1023] = __float2half(0.f); g_alo[o+1023] = __float2half(0.f); }
}

// ---------------------------------------------------------------------------
__global__ void k_padw_hi(const float* __restrict__ w) {
    int i = blockIdx.x * 256 + threadIdx.x;
    int n = i >> 10, k = i & 1023;
    float v = (k < DH) ? w[(size_t)n*DH + k] : 0.f;
    g_bhi[i] = __float2half(v);
}
__global__ void k_w_hi(const float* __restrict__ w) {
    int i = blockIdx.x * 256 + threadIdx.x;
    g_bhi[i] = __float2half(w[i]);
}

// ---------------------------------------------------------------------------
// k_rms (compact rows only)
// ---------------------------------------------------------------------------
__global__ void k_rms(const float* __restrict__ lnw) {
    int r = blockIdx.x;
    if (r >= g_Mp[0]) return;
    const float* hp = g_h2 + (size_t)r*DD;
    int tid = threadIdx.x;
    float v0 = hp[tid], v1 = hp[tid+256], v2 = hp[tid+512], v3 = hp[tid+768];
    __shared__ float red[256];
    red[tid] = v0*v0 + v1*v1 + v2*v2 + v3*v3;
    __syncthreads();
    for (int o = 128; o > 0; o >>= 1) {
        if (tid < o) red[tid] += red[tid + o];
        __syncthreads();
    }
    float inv = rsqrtf(red[0] * (1.0f/DD) + 1e-6f);
    size_t o = (size_t)r*DD;
    g_ahi[o+tid]     = __float2half(v0*inv*lnw[tid]);
    g_ahi[o+tid+256] = __float2half(v1*inv*lnw[tid+256]);
    g_ahi[o+tid+512] = __float2half(v2*inv*lnw[tid+512]);
    g_ahi[o+tid+768] = __float2half(v3*inv*lnw[tid+768]);
}

// ---------------------------------------------------------------------------
// Empty-row pipeline (fp32): rmsnorm(cif_b)*ln_w -> dot text_w -> fill tails
// ---------------------------------------------------------------------------
__global__ void k_empty1(const float* __restrict__ cb, const float* __restrict__ lnw) {
    int tid = threadIdx.x;
    float v0 = cb[tid], v1 = cb[tid+256], v2 = cb[tid+512], v3 = cb[tid+768];
    __shared__ float red[256];
    red[tid] = v0*v0 + v1*v1 + v2*v2 + v3*v3;
    __syncthreads();
    for (int o = 128; o > 0; o >>= 1) {
        if (tid < o) red[tid] += red[tid + o];
        __syncthreads();
    }
    float inv = rsqrtf(red[0] * (1.0f/DD) + 1e-6f);
    g_embed[tid]     = v0 * inv * lnw[tid];
    g_embed[tid+256] = v1 * inv * lnw[tid+256];
    g_embed[tid+512] = v2 * inv * lnw[tid+512];
    g_embed[tid+768] = v3 * inv * lnw[tid+768];
}
__global__ void k_empty2(const float* __restrict__ tw, const float* __restrict__ tb) {
    int c = blockIdx.x;                      // 4096 blocks
    int tid = threadIdx.x;                   // 256
    const float* wr = tw + (size_t)c*DD;
    float s = 0.f;
    #pragma unroll
    for (int i = 0; i < 4; i++)
        s += g_embed[tid + i*256] * wr[tid + i*256];
    __shared__ float red[256];
    red[tid] = s;
    __syncthreads();
    for (int o = 128; o > 0; o >>= 1) {
        if (tid < o) red[tid] += red[tid + o];
        __syncthreads();
    }
    if (tid == 0) g_outempty[c] = red[0] + tb[c];
}
__global__ void k_fill(float* __restrict__ out) {
    int r = blockIdx.x;                      // 6000
    int b = r / NTOK, n = r % NTOK;
    if (n < g_nt[b]) return;
    float4* dst = (float4*)(out + (size_t)r*DTXT);
    const float4* src = (const float4*)g_outempty;
    for (int i = threadIdx.x; i < DTXT/4; i += 256)
        dst[i] = src[i];
}

// ---------------------------------------------------------------------------
// fp16 tensor-core GEMM (proven R10 shape: 128x128, warp 64x32, BK=32).
// NPASS: 1 = A plain, 2 = A hi/lo. SCATTER: epilogue rows via rowmap.
// All row indices compact; CTAs beyond M' exit.
// ---------------------------------------------------------------------------
#define AROWB     80
#define ATILEB    (128*AROWB)

__device__ __forceinline__ void cp16(uint32_t dst, const void* src) {
    asm volatile("cp.async.cg.shared.global [%0], [%1], 16;"
                 :: "r"(dst), "l"(src) : "memory");
}
__device__ __forceinline__ void ldsm4(uint32_t r[4], uint32_t addr) {
    asm volatile("ldmatrix.sync.aligned.m8n8.x4.shared.b16 {%0,%1,%2,%3}, [%4];"
                 : "=r"(r[0]), "=r"(r[1]), "=r"(r[2]), "=r"(r[3]) : "r"(addr));
}
__device__ __forceinline__ void mma_h(float d[4], const uint32_t a[4],
                                      uint32_t b0, uint32_t b1) {
    asm volatile(
        "mma.sync.aligned.m16n8k16.row.col.f32.f16.f16.f32 "
        "{%0,%1,%2,%3}, {%4,%5,%6,%7}, {%8,%9}, {%0,%1,%2,%3};"
        : "+f"(d[0]), "+f"(d[1]), "+f"(d[2]), "+f"(d[3])
        : "r"(a[0]), "r"(a[1]), "r"(a[2]), "r"(a[3]), "r"(b0), "r"(b1));
}

template<int NPASS, bool SCATTER>
__global__ void __launch_bounds__(256)
gemm_h(int K,
       const __half* __restrict__ Ah, const __half* __restrict__ Al, int lda,
       const __half* __restrict__ Bh, int ldb,
       const float* __restrict__ bias,
       float* __restrict__ C, int ldc)
{
    constexpr int NA = (NPASS == 2) ? 2 : 1;
    constexpr uint32_t STAGEB = (NA + 1) * ATILEB;
    extern __shared__ __align__(128) char smem[];
    uint32_t sbase = (uint32_t)__cvta_generic_to_shared(smem);

    int M = g_Mp[0];
    int m0 = blockIdx.y * 128;
    if (m0 >= M) return;
    int tid  = threadIdx.x;
    int wid  = tid >> 5, lane = tid & 31;
    int g    = lane >> 2, tig = lane & 3;
    int n0   = blockIdx.x * 128;
    int wm   = (wid & 1) * 64;
    int wn   = (wid >> 1) * 32;

    float acc[4][4][4];
    #pragma unroll
    for (int i = 0; i < 4; i++)
        #pragma unroll
        for (int j = 0; j < 4; j++)
            #pragma unroll
            for (int q = 0; q < 4; q++) acc[i][j][q] = 0.f;

    const int nt = K >> 5;

    auto load_stage = [&](int s, int kt) {
        uint32_t st = sbase + (uint32_t)s * STAGEB;
        int k0 = kt << 5;
        #pragma unroll
        for (int c = tid; c < 512; c += 256) {
            int row = c >> 2, ch = (c & 3) << 4;
            int ke = k0 + (ch >> 1);
            int gm = m0 + row; if (gm >= M) gm = M - 1;
            uint32_t d = st + row*AROWB + ch;
            cp16(d, Ah + (size_t)gm*lda + ke);
            if (NPASS == 2) cp16(d + ATILEB, Al + (size_t)gm*lda + ke);
            cp16(st + NA*ATILEB + row*AROWB + ch, Bh + (size_t)(n0 + row)*ldb + ke);
        }
        asm volatile("cp.async.commit_group;" ::: "memory");
    };

    load_stage(0, 0);

    int quad = lane >> 3, qr = lane & 7;
    for (int kt = 0; kt < nt; kt++) {
        int buf = kt & 1;
        if (kt + 1 < nt) {
            load_stage(buf ^ 1, kt + 1);
            asm volatile("cp.async.wait_group 1;" ::: "memory");
        } else {
            asm volatile("cp.async.wait_group 0;" ::: "memory");
        }
        __syncthreads();

        uint32_t st = sbase + (uint32_t)buf * STAGEB;
        #pragma unroll
        for (int ks = 0; ks < 2; ks++) {
            int kc = ks * 16;
            uint32_t ka = (uint32_t)((kc + ((quad >> 1) << 3)) << 1);
            uint32_t arow = st + (uint32_t)(wm + ((quad & 1) << 3) + qr) * AROWB + ka;
            uint32_t brow = st + NA*ATILEB
                          + (uint32_t)(wn + ((quad & 1) << 3) + qr) * AROWB + ka;

            uint32_t ah[4][4], al[4][4], bh[2][4];
            #pragma unroll
            for (int mi = 0; mi < 4; mi++) {
                ldsm4(ah[mi], arow + mi*16*AROWB);
                if (NPASS == 2) ldsm4(al[mi], arow + ATILEB + mi*16*AROWB);
            }
            #pragma unroll
            for (int nb = 0; nb < 2; nb++)
                ldsm4(bh[nb], brow + nb*16*AROWB);

            #pragma unroll
            for (int mi = 0; mi < 4; mi++)
                #pragma unroll
                for (int ni = 0; ni < 4; ni++) {
                    int nb = ni >> 1, sel = ni & 1;
                    mma_h(acc[mi][ni], ah[mi], bh[nb][sel], bh[nb][sel+2]);
                    if (NPASS == 2)
                        mma_h(acc[mi][ni], al[mi], bh[nb][sel], bh[nb][sel+2]);
                }
        }
        __syncthreads();
    }

    #pragma unroll
    for (int mi = 0; mi < 4; mi++) {
        int row0 = m0 + wm + mi*16 + g;
        int row1 = row0 + 8;
        int o0 = (SCATTER && row0 < M) ? g_rowmap[row0] : row0;
        int o1 = (SCATTER && row1 < M) ? g_rowmap[row1] : row1;
        #pragma unroll
        for (int ni = 0; ni < 4; ni++) {
            int col = n0 + wn + ni*8 + 2*tig;
            float b0 = bias[col], b1 = bias[col+1];
            if (row0 < M) {
                float2 v = { acc[mi][ni][0] + b0, acc[mi][ni][1] + b1 };
                *reinterpret_cast<float2*>(C + (size_t)o0*ldc + col) = v;
            }
            if (row1 < M) {
                float2 v = { acc[mi][ni][2] + b0, acc[mi][ni][3] + b1 };
                *reinterpret_cast<float2*>(C + (size_t)o1*ldc + col) = v;
            }
        }
    }
}

// ---------------------------------------------------------------------------
__global__ void k_tail(float* __restrict__ out, int out_size) {
    int i = threadIdx.x;
    if (i < BB && out_size >= MM*DTXT + 2*BB) {
        out[MM*DTXT + i]      = (float)g_nt[i];
        out[MM*DTXT + BB + i] = g_numpred[i];
    }
}

// ---------------------------------------------------------------------------
extern "C" void kernel_launch(void* const* d_in, const int* in_sizes, int n_in,
                              void* d_out, int out_size) {
    const float* af     = (const float*)d_in[0];
    const float* cif_w  = (const float*)d_in[1];
    const float* cif_b  = (const float*)d_in[2];
    const float* ln_w   = (const float*)d_in[3];
    const float* text_w = (const float*)d_in[4];
    const float* text_b = (const float*)d_in[5];
    const void*  nf     = d_in[6];
    const void*  nt     = d_in[7];
    float* out = (float*)d_out;

    void *p_h2=0, *p_ahi=0, *p_alo=0, *p_bhi=0;
    cudaGetSymbolAddress(&p_h2,  g_h2);
    cudaGetSymbolAddress(&p_ahi, g_ahi);
    cudaGetSymbolAddress(&p_alo, g_alo);
    cudaGetSymbolAddress(&p_bhi, g_bhi);

    const int SMEM2 = 2 * 3 * ATILEB;   // 61440
    const int SMEM1 = 2 * 2 * ATILEB;   // 40960
    cudaFuncSetAttribute((const void*)gemm_h<2,false>, cudaFuncAttributeMaxDynamicSharedMemorySize, SMEM2);
    cudaFuncSetAttribute((const void*)gemm_h<1,true>,  cudaFuncAttributeMaxDynamicSharedMemorySize, SMEM1);
    cudaFuncSetAttribute((const void*)k_cif5,          cudaFuncAttributeMaxDynamicSharedMemorySize, CIF_SMEM);

    k_detect<<<1, 1>>>(nf, nt);
    k_empty1<<<1, 256>>>(cif_b, ln_w);              // fp32 empty-row pipeline
    k_empty2<<<DTXT, 256>>>(text_w, text_b);
    k_cif5<<<1, 512, CIF_SMEM>>>(af);
    k_fill<<<MM, 256>>>(out);                       // broadcast empty rows
    k_h1<<<MM, 256>>>(af);                          // compact -> g_ahi/g_alo
    k_padw_hi<<<(DD*DD)/256, 256>>>(cif_w);

    // cif_proj (compact): 2-pass
    {
        dim3 grid(DD/128, (MM + 127)/128);
        gemm_h<2,false><<<grid, 256, SMEM2>>>(1024,
            (const __half*)p_ahi, (const __half*)p_alo, LDH,
            (const __half*)p_bhi, 1024,
            cif_b, (float*)p_h2, DD);
    }
    k_rms<<<MM, 256>>>(ln_w);
    k_w_hi<<<(DTXT*DD)/256, 256>>>(text_w);

    // text_proj (compact, scatter epilogue): 1-pass
    {
        dim3 grid(DTXT/128, (MM + 127)/128);
        gemm_h<1,true><<<grid, 256, SMEM1>>>(1024,
            (const __half*)p_ahi, (const __half*)p_alo, LDH,
            (const __half*)p_bhi, DD,
            text_b, out, DTXT);
    }
    k_tail<<<1, 32>>>(out, out_size);
}